// round 1
// baseline (speedup 1.0000x reference)
#include <cuda_runtime.h>
#include <cuda_bf16.h>
#include <cstdint>

#define EPSV 1e-8f
#define FULLMASK 0xffffffffu

constexpr int Bb = 8;
constexpr int Ss = 2048;
constexpr int Dd = 1024;
constexpr int Hh = 1024;
constexpr int Mtot = Bb * Ss;   // 16384

// Scratch: [B][H][S] chain-contiguous layouts (device globals; no allocation).
__device__ float g_logret[(size_t)Bb * Hh * Ss];
__device__ float g_ninfo[(size_t)Bb * Hh * Ss];

// ---------------------------------------------------------------------------
// Kernel 1: fused triple SGEMM (z_f, z_i, z_h) + gate epilogue.
//   z[m][n] = sum_d X[m][d] * W[n][d]
// Tile: BM=128 (m = b*S+s), BN=64 (h), BK=16. 256 threads, 8x4 microtile x3.
// Epilogue writes logret/ninfo transposed to [B][H][S] via smem staging.
// ---------------------------------------------------------------------------
__global__ __launch_bounds__(256) void gate_gemm_kernel(
    const float* __restrict__ X,
    const float* __restrict__ Wf,
    const float* __restrict__ Wi,
    const float* __restrict__ Wh,
    const float* __restrict__ bf,
    const float* __restrict__ bi,
    const float* __restrict__ bh)
{
    // 40KB smem: As[2][16][128] (4096 floats) + Bs[2][3][16][64] (6144 floats)
    __shared__ __align__(16) float smem[2 * 16 * 128 + 2 * 3 * 16 * 64];
    float* As = smem;                  // buf*2048 + k*128 + m
    float* Bs = smem + 2 * 16 * 128;   // buf*3072 + g*1024 + k*64 + n

    const int tid  = threadIdx.x;
    const int col0 = blockIdx.x * 64;     // h offset
    const int row0 = blockIdx.y * 128;    // m offset (b*S+s)

    const int tx = tid & 15;              // n direction (16)
    const int ty = tid >> 4;              // m direction (16)
    const int m0 = ty * 8;
    const int n0 = tx * 4;

    float acc_f[8][4] = {};
    float acc_i[8][4] = {};
    float acc_h[8][4] = {};

    // Global-load index helpers
    const int a_m0 = tid >> 2;            // 0..63   (idx = tid)
    const int a_kq = (tid & 3) * 4;
    const int a_m1 = (tid + 256) >> 2;    // 64..127 (idx = tid+256)
    const int b_n  = tid >> 2;            // 0..63
    const int b_kq = (tid & 3) * 4;

    const float* Xa0 = X + (size_t)(row0 + a_m0) * Dd + a_kq;
    const float* Xa1 = X + (size_t)(row0 + a_m1) * Dd + a_kq;
    const float* Wfp = Wf + (size_t)(col0 + b_n) * Dd + b_kq;
    const float* Wip = Wi + (size_t)(col0 + b_n) * Dd + b_kq;
    const float* Whp = Wh + (size_t)(col0 + b_n) * Dd + b_kq;

    float4 pa0, pa1, pbf, pbi, pbh;

    // Preload tile 0 into buffer 0
    pa0 = *(const float4*)(Xa0);
    pa1 = *(const float4*)(Xa1);
    pbf = *(const float4*)(Wfp);
    pbi = *(const float4*)(Wip);
    pbh = *(const float4*)(Whp);
    {
        float* a = As + (a_kq) * 128;
        a[0 * 128 + a_m0] = pa0.x; a[1 * 128 + a_m0] = pa0.y;
        a[2 * 128 + a_m0] = pa0.z; a[3 * 128 + a_m0] = pa0.w;
        a[0 * 128 + a_m1] = pa1.x; a[1 * 128 + a_m1] = pa1.y;
        a[2 * 128 + a_m1] = pa1.z; a[3 * 128 + a_m1] = pa1.w;
        float* bb = Bs + (b_kq) * 64 + b_n;
        bb[0 * 64] = pbf.x; bb[1 * 64] = pbf.y; bb[2 * 64] = pbf.z; bb[3 * 64] = pbf.w;
        bb += 1024;
        bb[0 * 64] = pbi.x; bb[1 * 64] = pbi.y; bb[2 * 64] = pbi.z; bb[3 * 64] = pbi.w;
        bb += 1024;
        bb[0 * 64] = pbh.x; bb[1 * 64] = pbh.y; bb[2 * 64] = pbh.z; bb[3 * 64] = pbh.w;
    }
    __syncthreads();

    int buf = 0;
    const int NK = Dd / 16;  // 64

    for (int kt = 0; kt < NK; ++kt) {
        // Prefetch next tile into registers
        if (kt + 1 < NK) {
            const int koff = (kt + 1) * 16;
            pa0 = *(const float4*)(Xa0 + koff);
            pa1 = *(const float4*)(Xa1 + koff);
            pbf = *(const float4*)(Wfp + koff);
            pbi = *(const float4*)(Wip + koff);
            pbh = *(const float4*)(Whp + koff);
        }

        // Compute on current buffer
        const float* Ab = As + buf * 2048;
        const float* Bb_ = Bs + buf * 3072;
#pragma unroll
        for (int kk = 0; kk < 16; ++kk) {
            float4 a0 = *(const float4*)(Ab + kk * 128 + m0);
            float4 a1 = *(const float4*)(Ab + kk * 128 + m0 + 4);
            float4 vf = *(const float4*)(Bb_ + 0    + kk * 64 + n0);
            float4 vi = *(const float4*)(Bb_ + 1024 + kk * 64 + n0);
            float4 vh = *(const float4*)(Bb_ + 2048 + kk * 64 + n0);
            float a[8] = {a0.x, a0.y, a0.z, a0.w, a1.x, a1.y, a1.z, a1.w};
            float bfv[4] = {vf.x, vf.y, vf.z, vf.w};
            float biv[4] = {vi.x, vi.y, vi.z, vi.w};
            float bhv[4] = {vh.x, vh.y, vh.z, vh.w};
#pragma unroll
            for (int i = 0; i < 8; ++i) {
#pragma unroll
                for (int j = 0; j < 4; ++j) {
                    acc_f[i][j] = fmaf(a[i], bfv[j], acc_f[i][j]);
                    acc_i[i][j] = fmaf(a[i], biv[j], acc_i[i][j]);
                    acc_h[i][j] = fmaf(a[i], bhv[j], acc_h[i][j]);
                }
            }
        }

        // Store prefetched tile into the other buffer
        if (kt + 1 < NK) {
            const int nb = buf ^ 1;
            float* a = As + nb * 2048 + (a_kq) * 128;
            a[0 * 128 + a_m0] = pa0.x; a[1 * 128 + a_m0] = pa0.y;
            a[2 * 128 + a_m0] = pa0.z; a[3 * 128 + a_m0] = pa0.w;
            a[0 * 128 + a_m1] = pa1.x; a[1 * 128 + a_m1] = pa1.y;
            a[2 * 128 + a_m1] = pa1.z; a[3 * 128 + a_m1] = pa1.w;
            float* bb = Bs + nb * 3072 + (b_kq) * 64 + b_n;
            bb[0 * 64] = pbf.x; bb[1 * 64] = pbf.y; bb[2 * 64] = pbf.z; bb[3 * 64] = pbf.w;
            bb += 1024;
            bb[0 * 64] = pbi.x; bb[1 * 64] = pbi.y; bb[2 * 64] = pbi.z; bb[3 * 64] = pbi.w;
            bb += 1024;
            bb[0 * 64] = pbh.x; bb[1 * 64] = pbh.y; bb[2 * 64] = pbh.z; bb[3 * 64] = pbh.w;
            __syncthreads();
            buf = nb;
        }
    }

    // ---------------- Epilogue: gates -> logret / ninfo ----------------
    __syncthreads();   // all compute reads of smem done before we overwrite

    const int bidx = row0 >> 11;            // row0 / S  (tile never straddles b)
    const int s0   = row0 & (Ss - 1);

    float bfb[4], bib[4], bhb[4];
#pragma unroll
    for (int j = 0; j < 4; ++j) {
        bfb[j] = bf[col0 + n0 + j];
        bib[j] = bi[col0 + n0 + j];
        bhb[j] = bh[col0 + n0 + j];
    }

    float* tile = smem;  // [64][129] staging = 8256 floats <= 10240 available

    // Pass 1: logret
#pragma unroll
    for (int i = 0; i < 8; ++i) {
#pragma unroll
        for (int j = 0; j < 4; ++j) {
            float zf = acc_f[i][j] + bfb[j];
            float zi = acc_i[i][j] + bib[j];
            float fg = 1.0f / (1.0f + expf(-zf));
            float ig = 1.0f / (1.0f + expf(-zi));
            float gs = fg + ig + EPSV;
            float lr = logf(fg / gs + EPSV);
            tile[(n0 + j) * 129 + (m0 + i)] = lr;
        }
    }
    __syncthreads();
#pragma unroll
    for (int r = 0; r < 32; ++r) {
        int idx = r * 256 + tid;
        int nl = idx >> 7;
        int ml = idx & 127;
        g_logret[((size_t)(bidx * Hh + col0 + nl)) * Ss + s0 + ml] = tile[nl * 129 + ml];
    }
    __syncthreads();

    // Pass 2: ninfo = (i / (f+i+eps)) * (z_h + b_h)
#pragma unroll
    for (int i = 0; i < 8; ++i) {
#pragma unroll
        for (int j = 0; j < 4; ++j) {
            float zf = acc_f[i][j] + bfb[j];
            float zi = acc_i[i][j] + bib[j];
            float fg = 1.0f / (1.0f + expf(-zf));
            float ig = 1.0f / (1.0f + expf(-zi));
            float gs = fg + ig + EPSV;
            float inorm = ig / gs;
            float cand = acc_h[i][j] + bhb[j];
            tile[(n0 + j) * 129 + (m0 + i)] = inorm * cand;
        }
    }
    __syncthreads();
#pragma unroll
    for (int r = 0; r < 32; ++r) {
        int idx = r * 256 + tid;
        int nl = idx >> 7;
        int ml = idx & 127;
        g_ninfo[((size_t)(bidx * Hh + col0 + nl)) * Ss + s0 + ml] = tile[nl * 129 + ml];
    }
}

// ---------------------------------------------------------------------------
// Kernel 2: per-(b,h) chain scan.
//   L[t] = cumsum(logret); scaling[t] = exp(L_last - L[t-1]);
//   hidden[t] = cumsum(scaling * ninfo) + exp(L[t]) * h0
// 1 warp per chain; 32 warps/block = 32 consecutive h of one b.
// Output staged through smem for coalesced [B,S,H] writes.
// ---------------------------------------------------------------------------
__global__ __launch_bounds__(1024) void scan_kernel(
    const float* __restrict__ h0,
    float* __restrict__ out)
{
    __shared__ float tile[32][33];

    const int b    = blockIdx.y;
    const int hc0  = blockIdx.x * 32;
    const int w    = threadIdx.x >> 5;
    const int lane = threadIdx.x & 31;
    const int h    = hc0 + w;

    const size_t base = ((size_t)(b * Hh + h)) * Ss;
    const float* lrp = g_logret + base;
    const float* nfp = g_ninfo + base;
    const float hinit = h0[b * Hh + h];

    // Pass 1: total log-retention for this chain
    float s = 0.0f;
    for (int t = lane; t < Ss; t += 32) s += lrp[t];
#pragma unroll
    for (int o = 16; o > 0; o >>= 1) s += __shfl_xor_sync(FULLMASK, s, o);
    const float Llast = s;

    // Pass 2: joint scan
    float carryL = 0.0f;
    float carryH = 0.0f;
    for (int t0 = 0; t0 < Ss; t0 += 32) {
        float lr = lrp[t0 + lane];
        float nf = nfp[t0 + lane];

        // inclusive scan of lr
        float incl = lr;
#pragma unroll
        for (int o = 1; o < 32; o <<= 1) {
            float v = __shfl_up_sync(FULLMASK, incl, o);
            if (lane >= o) incl += v;
        }
        float excl = __shfl_up_sync(FULLMASK, incl, 1);
        if (lane == 0) excl = 0.0f;

        float Lt    = carryL + incl;
        float Lprev = carryL + excl;
        float scaling = expf(Llast - Lprev);
        float term = scaling * nf;

        // inclusive scan of term
        float cs = term;
#pragma unroll
        for (int o = 1; o < 32; o <<= 1) {
            float v = __shfl_up_sync(FULLMASK, cs, o);
            if (lane >= o) cs += v;
        }

        float hid = carryH + cs + expf(Lt) * hinit;

        carryL += __shfl_sync(FULLMASK, incl, 31);
        carryH += __shfl_sync(FULLMASK, cs, 31);

        // Stage + coalesced write: tile[t_local][h_local]
        tile[lane][w] = hid;
        __syncthreads();
        out[((size_t)b * Ss + t0 + w) * Hh + hc0 + lane] = tile[w][lane];
        __syncthreads();
    }
}

// ---------------------------------------------------------------------------
extern "C" void kernel_launch(void* const* d_in, const int* in_sizes, int n_in,
                              void* d_out, int out_size)
{
    const float* X  = (const float*)d_in[0];
    const float* h0 = (const float*)d_in[1];
    const float* Wf = (const float*)d_in[2];
    const float* bf = (const float*)d_in[3];
    const float* Wi = (const float*)d_in[4];
    const float* bi = (const float*)d_in[5];
    const float* Wh = (const float*)d_in[6];
    const float* bh = (const float*)d_in[7];
    float* out = (float*)d_out;

    dim3 g1(Hh / 64, Mtot / 128);   // (16, 128)
    gate_gemm_kernel<<<g1, 256>>>(X, Wf, Wi, Wh, bf, bi, bh);

    dim3 g2(Hh / 32, Bb);           // (32, 8)
    scan_kernel<<<g2, 1024>>>(h0, out);
}

// round 4
// speedup vs baseline: 2.8469x; 2.8469x over previous
#include <cuda_runtime.h>
#include <cuda_bf16.h>
#include <cstdint>

#define EPSV 1e-8f
#define FULLMASK 0xffffffffu

constexpr int Bb = 8;
constexpr int Ss = 2048;
constexpr int Dd = 1024;
constexpr int Hh = 1024;
constexpr int Mtot = Bb * Ss;      // 16384

// ------------------------- device scratch (no allocs) -----------------------
__device__ __nv_bfloat16 g_Xhi[(size_t)Mtot * Dd];
__device__ __nv_bfloat16 g_Xlo[(size_t)Mtot * Dd];
__device__ __nv_bfloat16 g_Whi[3][(size_t)Hh * Dd];
__device__ __nv_bfloat16 g_Wlo[3][(size_t)Hh * Dd];
__device__ float g_logret[(size_t)Bb * Hh * Ss];   // [b][h][s]
__device__ float g_ninfo[(size_t)Bb * Hh * Ss];

// ------------------------------ helpers -------------------------------------
__device__ __forceinline__ uint32_t smem_u32(const void* p) {
    uint32_t a;
    asm("{ .reg .u64 t; cvta.to.shared.u64 t, %1; cvt.u32.u64 %0, t; }"
        : "=r"(a) : "l"(p));
    return a;
}
__device__ __forceinline__ void cp16(uint32_t dst, const void* src) {
    asm volatile("cp.async.cg.shared.global [%0], [%1], 16;"
                 :: "r"(dst), "l"(src) : "memory");
}
__device__ __forceinline__ void cp_commit() {
    asm volatile("cp.async.commit_group;" ::: "memory");
}
template <int N>
__device__ __forceinline__ void cp_wait() {
    asm volatile("cp.async.wait_group %0;" :: "n"(N) : "memory");
}
__device__ __forceinline__ uint32_t swz(uint32_t x) {   // SW128
    return x ^ ((x >> 3) & 0x70);
}
__device__ __forceinline__ void ldsm4(uint32_t& r0, uint32_t& r1,
                                      uint32_t& r2, uint32_t& r3, uint32_t addr) {
    asm volatile("ldmatrix.sync.aligned.m8n8.x4.shared.b16 {%0,%1,%2,%3}, [%4];"
                 : "=r"(r0), "=r"(r1), "=r"(r2), "=r"(r3) : "r"(addr));
}
__device__ __forceinline__ void mma16816(float* c,
                                         uint32_t a0, uint32_t a1, uint32_t a2, uint32_t a3,
                                         uint32_t b0, uint32_t b1) {
    asm volatile(
        "mma.sync.aligned.m16n8k16.row.col.f32.bf16.bf16.f32 "
        "{%0,%1,%2,%3}, {%4,%5,%6,%7}, {%8,%9}, {%0,%1,%2,%3};"
        : "+f"(c[0]), "+f"(c[1]), "+f"(c[2]), "+f"(c[3])
        : "r"(a0), "r"(a1), "r"(a2), "r"(a3), "r"(b0), "r"(b1));
}

// -------------------------- conversion kernels -------------------------------
__global__ __launch_bounds__(256) void convert_x_kernel(const float* __restrict__ X) {
    size_t i = ((size_t)blockIdx.x * blockDim.x + threadIdx.x) * 4;
    float4 v = *(const float4*)(X + i);
    float f[4] = {v.x, v.y, v.z, v.w};
    __nv_bfloat16 h[4], l[4];
#pragma unroll
    for (int j = 0; j < 4; ++j) {
        h[j] = __float2bfloat16_rn(f[j]);
        l[j] = __float2bfloat16_rn(f[j] - __bfloat162float(h[j]));
    }
    *(uint2*)(g_Xhi + i) = *(uint2*)h;
    *(uint2*)(g_Xlo + i) = *(uint2*)l;
}
__global__ __launch_bounds__(256) void convert_w_kernel(const float* __restrict__ W, int gate) {
    size_t i = ((size_t)blockIdx.x * blockDim.x + threadIdx.x) * 4;
    float4 v = *(const float4*)(W + i);
    float f[4] = {v.x, v.y, v.z, v.w};
    __nv_bfloat16 h[4], l[4];
#pragma unroll
    for (int j = 0; j < 4; ++j) {
        h[j] = __float2bfloat16_rn(f[j]);
        l[j] = __float2bfloat16_rn(f[j] - __bfloat162float(h[j]));
    }
    *(uint2*)(g_Whi[gate] + i) = *(uint2*)h;
    *(uint2*)(g_Wlo[gate] + i) = *(uint2*)l;
}

// ------------------------------ fused GEMM -----------------------------------
// CTA tile: M=128 (b*S+s) x N=64 (h), all 3 gates. K stepped in chunks of 64.
// Stage layout (80 KB): Xhi[16K] Xlo[16K] Whi[3][8K] Wlo[3][8K], rows = 128B SW128.
constexpr int BK = 64;
constexpr int NK = Dd / BK;               // 16
constexpr int STAGE_B = 80 * 1024;
constexpr uint32_t OFF_XHI = 0;
constexpr uint32_t OFF_XLO = 16384;
constexpr uint32_t OFF_WHI = 32768;       // + g*8192
constexpr uint32_t OFF_WLO = 57344;       // + g*8192

extern __shared__ __align__(1024) char dynsmem[];

__device__ __forceinline__ void load_stage(uint32_t sb, int tid, int kt,
                                           int row0, int col0) {
    const int kb = kt * BK;
#pragma unroll
    for (int i = 0; i < 4; ++i) {                 // X: c in [0,1024)
        int c = tid + i * 256;
        int r = c >> 3, ch = c & 7;
        uint32_t so = swz((uint32_t)(r * 128 + ch * 16));
        size_t ga = (size_t)(row0 + r) * Dd + kb + ch * 8;
        cp16(sb + OFF_XHI + so, g_Xhi + ga);
        cp16(sb + OFF_XLO + so, g_Xlo + ga);
    }
#pragma unroll
    for (int i = 0; i < 6; ++i) {                 // W: d in [0,1536)
        int d = tid + i * 256;
        int r = d >> 3, ch = d & 7;
        int g = r >> 6, n = r & 63;
        uint32_t so = (uint32_t)(g * 8192) + swz((uint32_t)(n * 128 + ch * 16));
        size_t gb = (size_t)(col0 + n) * Dd + kb + ch * 8;
        cp16(sb + OFF_WHI + so, g_Whi[g] + gb);
        cp16(sb + OFF_WLO + so, g_Wlo[g] + gb);
    }
}

__global__ __launch_bounds__(256, 1) void gemm_fused_kernel(
    const float* __restrict__ bF,
    const float* __restrict__ bI,
    const float* __restrict__ bH)
{
    const int tid  = threadIdx.x;
    const int lane = tid & 31;
    const int wid  = tid >> 5;
    const int col0 = blockIdx.x * 64;       // h
    const int row0 = blockIdx.y * 128;      // m = b*S+s

    const int warpM = wid >> 1;             // 0..3
    const int warpN = wid & 1;              // 0..1
    const int m0w = warpM * 32;
    const int n0w = warpN * 32;

    const uint32_t sbase = smem_u32(dynsmem);

    // lane-derived ldmatrix addressing
    const int rA0 = m0w + (lane & 15);                    // msub0 rows
    const int rA1 = rA0 + 16;                             // msub1
    const uint32_t cbA = (uint32_t)(lane >> 4) * 16;      // k8 chunk within k16
    const int rB0 = n0w + (lane >> 4) * 8 + (lane & 7);   // nsubs {0,1}
    const int rB1 = rB0 + 16;                             // nsubs {2,3}
    const uint32_t cbB = (uint32_t)((lane >> 3) & 1) * 16;

    float acc[3][2][4][4];
#pragma unroll
    for (int g = 0; g < 3; ++g)
#pragma unroll
        for (int ms = 0; ms < 2; ++ms)
#pragma unroll
            for (int ns = 0; ns < 4; ++ns)
#pragma unroll
                for (int j = 0; j < 4; ++j) acc[g][ms][ns][j] = 0.0f;

    // prologue
    load_stage(sbase, tid, 0, row0, col0);
    cp_commit();

    for (int kt = 0; kt < NK; ++kt) {
        const uint32_t sb = sbase + (uint32_t)(kt & 1) * STAGE_B;
        if (kt + 1 < NK) {
            load_stage(sbase + (uint32_t)((kt + 1) & 1) * STAGE_B, tid, kt + 1, row0, col0);
            cp_commit();
            cp_wait<1>();
        } else {
            cp_wait<0>();
        }
        __syncthreads();

#pragma unroll
        for (int ks = 0; ks < 4; ++ks) {
            const uint32_t kofs = (uint32_t)ks * 32;
            uint32_t ah[8], al[8];
            ldsm4(ah[0], ah[1], ah[2], ah[3],
                  sb + OFF_XHI + swz((uint32_t)rA0 * 128 + kofs + cbA));
            ldsm4(ah[4], ah[5], ah[6], ah[7],
                  sb + OFF_XHI + swz((uint32_t)rA1 * 128 + kofs + cbA));
            ldsm4(al[0], al[1], al[2], al[3],
                  sb + OFF_XLO + swz((uint32_t)rA0 * 128 + kofs + cbA));
            ldsm4(al[4], al[5], al[6], al[7],
                  sb + OFF_XLO + swz((uint32_t)rA1 * 128 + kofs + cbA));
#pragma unroll
            for (int g = 0; g < 3; ++g) {
                const uint32_t whb = sb + OFF_WHI + (uint32_t)g * 8192;
                const uint32_t wlb = sb + OFF_WLO + (uint32_t)g * 8192;
                uint32_t bh[8], bl[8];
                ldsm4(bh[0], bh[1], bh[2], bh[3], whb + swz((uint32_t)rB0 * 128 + kofs + cbB));
                ldsm4(bh[4], bh[5], bh[6], bh[7], whb + swz((uint32_t)rB1 * 128 + kofs + cbB));
                ldsm4(bl[0], bl[1], bl[2], bl[3], wlb + swz((uint32_t)rB0 * 128 + kofs + cbB));
                ldsm4(bl[4], bl[5], bl[6], bl[7], wlb + swz((uint32_t)rB1 * 128 + kofs + cbB));
#pragma unroll
                for (int ms = 0; ms < 2; ++ms) {
                    const uint32_t* A_hi = ah + ms * 4;
                    const uint32_t* A_lo = al + ms * 4;
#pragma unroll
                    for (int ns = 0; ns < 4; ++ns) {
                        float* c = acc[g][ms][ns];
                        mma16816(c, A_hi[0], A_hi[1], A_hi[2], A_hi[3], bh[ns * 2], bh[ns * 2 + 1]);
                        mma16816(c, A_hi[0], A_hi[1], A_hi[2], A_hi[3], bl[ns * 2], bl[ns * 2 + 1]);
                        mma16816(c, A_lo[0], A_lo[1], A_lo[2], A_lo[3], bh[ns * 2], bh[ns * 2 + 1]);
                    }
                }
            }
        }
        __syncthreads();   // compute done before this buffer is overwritten
    }

    // ---------------- epilogue: gates -> logret/ninfo ([B,H,S]) --------------
    const int bidx = row0 >> 11;
    const int s0   = row0 & (Ss - 1);
    float* tile = (float*)dynsmem;          // [64][129] staging

    // hoist bias values: each thread touches 8 distinct n columns
    float bfv[8], biv[8], bhv[8];
#pragma unroll
    for (int ns = 0; ns < 4; ++ns)
#pragma unroll
        for (int q = 0; q < 2; ++q) {
            const int nl = n0w + ns * 8 + (lane & 3) * 2 + q;
            bfv[ns * 2 + q] = __ldg(bF + col0 + nl);
            biv[ns * 2 + q] = __ldg(bI + col0 + nl);
            bhv[ns * 2 + q] = __ldg(bH + col0 + nl);
        }

#pragma unroll
    for (int pass = 0; pass < 2; ++pass) {
#pragma unroll
        for (int ms = 0; ms < 2; ++ms)
#pragma unroll
            for (int ns = 0; ns < 4; ++ns)
#pragma unroll
                for (int j = 0; j < 4; ++j) {
                    const int nl = n0w + ns * 8 + (lane & 3) * 2 + (j & 1);
                    const int ml = m0w + ms * 16 + (j >> 1) * 8 + (lane >> 2);
                    const int bi8 = ns * 2 + (j & 1);
                    float zf = acc[0][ms][ns][j] + bfv[bi8];
                    float zi = acc[1][ms][ns][j] + biv[bi8];
                    float fg = 1.0f / (1.0f + expf(-zf));
                    float ig = 1.0f / (1.0f + expf(-zi));
                    float gs = fg + ig + EPSV;
                    float v;
                    if (pass == 0) {
                        v = logf(fg / gs + EPSV);
                    } else {
                        float zh = acc[2][ms][ns][j] + bhv[bi8];
                        v = (ig / gs) * zh;
                    }
                    tile[nl * 129 + ml] = v;
                }
        __syncthreads();
        float* dst = (pass == 0) ? g_logret : g_ninfo;
#pragma unroll
        for (int r = 0; r < 32; ++r) {
            int idx = r * 256 + tid;
            int nl = idx >> 7;
            int ml = idx & 127;
            dst[((size_t)(bidx * Hh + col0 + nl)) * Ss + s0 + ml] = tile[nl * 129 + ml];
        }
        __syncthreads();
    }
}

// ------------------------------- scan kernel ---------------------------------
__global__ __launch_bounds__(1024) void scan_kernel(
    const float* __restrict__ h0,
    float* __restrict__ out)
{
    __shared__ float tile[32][33];

    const int b    = blockIdx.y;
    const int hc0  = blockIdx.x * 32;
    const int w    = threadIdx.x >> 5;
    const int lane = threadIdx.x & 31;
    const int h    = hc0 + w;

    const size_t base = ((size_t)(b * Hh + h)) * Ss;
    const float* lrp = g_logret + base;
    const float* nfp = g_ninfo + base;
    const float hinit = h0[b * Hh + h];

    float s = 0.0f;
    for (int t = lane; t < Ss; t += 32) s += lrp[t];
#pragma unroll
    for (int o = 16; o > 0; o >>= 1) s += __shfl_xor_sync(FULLMASK, s, o);
    const float Llast = s;

    float carryL = 0.0f;
    float carryH = 0.0f;
    for (int t0 = 0; t0 < Ss; t0 += 32) {
        float lr = lrp[t0 + lane];
        float nf = nfp[t0 + lane];

        float incl = lr;
#pragma unroll
        for (int o = 1; o < 32; o <<= 1) {
            float v = __shfl_up_sync(FULLMASK, incl, o);
            if (lane >= o) incl += v;
        }
        float excl = __shfl_up_sync(FULLMASK, incl, 1);
        if (lane == 0) excl = 0.0f;

        float Lt    = carryL + incl;
        float Lprev = carryL + excl;
        float scaling = expf(Llast - Lprev);
        float term = scaling * nf;

        float cs = term;
#pragma unroll
        for (int o = 1; o < 32; o <<= 1) {
            float v = __shfl_up_sync(FULLMASK, cs, o);
            if (lane >= o) cs += v;
        }

        float hid = carryH + cs + expf(Lt) * hinit;

        carryL += __shfl_sync(FULLMASK, incl, 31);
        carryH += __shfl_sync(FULLMASK, cs, 31);

        tile[lane][w] = hid;
        __syncthreads();
        out[((size_t)b * Ss + t0 + w) * Hh + hc0 + lane] = tile[w][lane];
        __syncthreads();
    }
}

// -----------------------------------------------------------------------------
extern "C" void kernel_launch(void* const* d_in, const int* in_sizes, int n_in,
                              void* d_out, int out_size)
{
    const float* X  = (const float*)d_in[0];
    const float* h0 = (const float*)d_in[1];
    const float* Wf = (const float*)d_in[2];
    const float* bf = (const float*)d_in[3];
    const float* Wi = (const float*)d_in[4];
    const float* bi = (const float*)d_in[5];
    const float* Wh = (const float*)d_in[6];
    const float* bh = (const float*)d_in[7];
    float* out = (float*)d_out;

    cudaFuncSetAttribute(gemm_fused_kernel,
                         cudaFuncAttributeMaxDynamicSharedMemorySize,
                         2 * STAGE_B);

    convert_x_kernel<<<(Mtot * Dd) / 4 / 256, 256>>>(X);
    convert_w_kernel<<<(Hh * Dd) / 4 / 256, 256>>>(Wf, 0);
    convert_w_kernel<<<(Hh * Dd) / 4 / 256, 256>>>(Wi, 1);
    convert_w_kernel<<<(Hh * Dd) / 4 / 256, 256>>>(Wh, 2);

    dim3 gg(Hh / 64, Mtot / 128);       // (16, 128), n-fastest for X reuse
    gemm_fused_kernel<<<gg, 256, 2 * STAGE_B>>>(bf, bi, bh);

    dim3 gs(Hh / 32, Bb);               // (32, 8)
    scan_kernel<<<gs, 1024>>>(h0, out);
}